// round 6
// baseline (speedup 1.0000x reference)
#include <cuda_runtime.h>
#include <cuda_bf16.h>
#include <math.h>

// Problem constants
#define T_STEPS 512
#define BATCH   128
#define HDIM    512
#define HDIM3   1536

typedef unsigned long long u64;

// ---------------------------------------------------------------------------
// Packed f32x2 helpers (Blackwell fma.rn.f32x2 — 2 FMAs per instruction).
// ---------------------------------------------------------------------------
__device__ __forceinline__ u64 pk2_(float lo, float hi) {
    u64 r;
    asm("mov.b64 %0, {%1, %2};"
        : "=l"(r) : "r"(__float_as_uint(lo)), "r"(__float_as_uint(hi)));
    return r;
}
__device__ __forceinline__ void upk2_(u64 v, float& lo, float& hi) {
    unsigned int a, b_;
    asm("mov.b64 {%0, %1}, %2;" : "=r"(a), "=r"(b_) : "l"(v));
    lo = __uint_as_float(a);
    hi = __uint_as_float(b_);
}
__device__ __forceinline__ u64 ffma2_(u64 a, u64 b, u64 c) {
    u64 d;
    asm("fma.rn.f32x2 %0, %1, %2, %3;" : "=l"(d) : "l"(a), "l"(b), "l"(c));
    return d;
}
__device__ __forceinline__ u64 fadd2_(u64 a, u64 b) {
    u64 d;
    asm("add.rn.f32x2 %0, %1, %2;" : "=l"(d) : "l"(a), "l"(b));
    return d;
}

// ---------------------------------------------------------------------------
// Scratch: gi [T,B,3H]; h ping-pong stored TRANSPOSED *and duplicated*:
// g_hd[buf][k*128+b] = {h,h} as f32x2 (so the GEMV operand needs no packing).
// ---------------------------------------------------------------------------
__device__ __align__(16) float g_gi[(size_t)T_STEPS * BATCH * HDIM3];
__device__ __align__(16) u64 g_hd[2][BATCH * HDIM];
__device__ unsigned int g_arrive = 0;
__device__ unsigned int g_release = 0;

__global__ void reset_barrier_kernel() {
    if (threadIdx.x == 0) { g_arrive = 0; g_release = 0; }
}

// ---------------------------------------------------------------------------
// Grid-wide barrier, epoch-counter style (counters reset per launch by
// reset_barrier_kernel, so monotonic epochs are safe under graph replay).
// Release of epoch e requires all SCAN_BLOCKS arrivals for e, so epochs
// serialize correctly. Acquire-spin with nanosleep backoff.
// ---------------------------------------------------------------------------
#define SCAN_BLOCKS 128

__device__ __forceinline__ void gbar(unsigned epoch) {
    __syncthreads();
    if (threadIdx.x == 0) {
        unsigned ticket;
        asm volatile("atom.acq_rel.gpu.add.u32 %0, [%1], 1;"
                     : "=r"(ticket) : "l"(&g_arrive) : "memory");
        if (ticket == epoch * SCAN_BLOCKS - 1) {
            asm volatile("st.release.gpu.u32 [%0], %1;"
                         :: "l"(&g_release), "r"(epoch) : "memory");
        } else {
            unsigned r;
            while (1) {
                asm volatile("ld.acquire.gpu.u32 %0, [%1];"
                             : "=r"(r) : "l"(&g_release) : "memory");
                if ((int)(r - epoch) >= 0) break;
                __nanosleep(8);
            }
        }
    }
    __syncthreads();
}

// ---------------------------------------------------------------------------
// Pre-GEMM: gi[m,n] = sum_k x[m,k]*Wi[k,n] + bi[n].  M=65536, N=1536, K=512.
// 128x128 tile, 8x8/thread via FFMA2; As stored as duplicated {a,a} pairs,
// Bs read as adjacent-column pairs -> zero pack MOVs in the inner loop.
// ---------------------------------------------------------------------------
#define BM 128
#define BN 128
#define BKK 16

__global__ __launch_bounds__(256) void gemm_gi_kernel(
    const float* __restrict__ X, const float* __restrict__ Wi,
    const float* __restrict__ bi, float* __restrict__ gi)
{
    __shared__ __align__(16) u64 As2[BKK][BM];    // 16 KB, {a,a} dup pairs
    __shared__ __align__(16) float Bs[BKK][BN];   // 8 KB

    const int m0 = blockIdx.y * BM;
    const int n0 = blockIdx.x * BN;
    const int tid = threadIdx.x;

    const int arow = tid >> 2;          // 0..63
    const int acol = (tid & 3) * 4;     // 0,4,8,12
    const int brow = tid >> 5;          // 0..7
    const int bcol = (tid & 31) * 4;

    const int tr = tid >> 4;            // 0..15
    const int tc = tid & 15;            // 0..15

    u64 acc2[8][4];
#pragma unroll
    for (int i = 0; i < 8; i++)
#pragma unroll
        for (int j = 0; j < 4; j++) acc2[i][j] = 0ull;

    for (int k0 = 0; k0 < HDIM; k0 += BKK) {
#pragma unroll
        for (int h = 0; h < 2; h++) {
            int r = arow + 64 * h;
            float4 v = *(const float4*)&X[(size_t)(m0 + r) * HDIM + k0 + acol];
            As2[acol + 0][r] = pk2_(v.x, v.x);
            As2[acol + 1][r] = pk2_(v.y, v.y);
            As2[acol + 2][r] = pk2_(v.z, v.z);
            As2[acol + 3][r] = pk2_(v.w, v.w);
        }
#pragma unroll
        for (int h = 0; h < 2; h++) {
            int r = brow + 8 * h;
            *(float4*)&Bs[r][bcol] =
                *(const float4*)&Wi[(size_t)(k0 + r) * HDIM3 + n0 + bcol];
        }
        __syncthreads();

#pragma unroll
        for (int k = 0; k < BKK; k++) {
            const ulonglong2* a2 = (const ulonglong2*)&As2[k][tr * 8];
            ulonglong2 av0 = a2[0], av1 = a2[1], av2 = a2[2], av3 = a2[3];
            const ulonglong2* b2 = (const ulonglong2*)&Bs[k][tc * 8];
            ulonglong2 bb0 = b2[0], bb1 = b2[1];
            u64 av[8] = {av0.x, av0.y, av1.x, av1.y, av2.x, av2.y, av3.x, av3.y};
            u64 bv[4] = {bb0.x, bb0.y, bb1.x, bb1.y};
#pragma unroll
            for (int i = 0; i < 8; i++)
#pragma unroll
                for (int j = 0; j < 4; j++)
                    acc2[i][j] = ffma2_(av[i], bv[j], acc2[i][j]);
        }
        __syncthreads();
    }

#pragma unroll
    for (int i = 0; i < 8; i++) {
        int m = m0 + tr * 8 + i;
#pragma unroll
        for (int jq = 0; jq < 2; jq++) {
            int n = n0 + tc * 8 + jq * 4;
            float4 o;
            upk2_(acc2[i][jq * 2 + 0], o.x, o.y);
            upk2_(acc2[i][jq * 2 + 1], o.z, o.w);
            o.x += bi[n + 0];
            o.y += bi[n + 1];
            o.z += bi[n + 2];
            o.w += bi[n + 3];
            *(float4*)&gi[(size_t)m * HDIM3 + n] = o;
        }
    }
}

// ---------------------------------------------------------------------------
// Persistent scan: 128 blocks x 512 threads. Block owns h-cols j0..j0+3
// (12 Wh columns). 4-way k-split; quarter q reduces k in [q*128,(q+1)*128).
// wh_s holds column-PAIRS adjacently -> LDS.128 yields 2 packed f32x2
// operands directly. h read as pre-duplicated {h,h} via LDG.64.
// Inner loop per k: 3 LDS.128 + 6 FFMA2, zero pack MOVs.
// ---------------------------------------------------------------------------
#define SCAN_THREADS 512
#define KSPLIT 128           // k per quarter
#define JCHUNK 4

__device__ __forceinline__ float fast_sigmoid(float x) {
    return 1.0f / (1.0f + __expf(-x));
}
__device__ __forceinline__ float fast_tanh(float x) {
    return 2.0f / (1.0f + __expf(-2.0f * x)) - 1.0f;
}

__global__ __launch_bounds__(SCAN_THREADS) void scan_kernel(
    const float* __restrict__ h0, const float* __restrict__ Wh,
    const float* __restrict__ bhn,
    float* __restrict__ out_h, float* __restrict__ out_ys)
{
    __shared__ __align__(16) float wh_s[HDIM * 12];   // 24 KB: [k][12] cols
    __shared__ __align__(16) u64 red2[3][6 * BATCH];  // 18 KB partial dumps

    const int tid = threadIdx.x;
    const int b = tid & (BATCH - 1);      // batch row
    const int quarter = tid >> 7;         // 0..3
    const int kbase = quarter * KSPLIT;
    const int j0 = blockIdx.x * JCHUNK;

    // wh_s[k*12 + gate*4 + cc] = Wh[k][gate*H + j0 + cc]; pairs (cc 0,1) and
    // (cc 2,3) are adjacent -> natural f32x2 operands.
    for (int idx = tid; idx < HDIM * 12; idx += SCAN_THREADS) {
        int kk = idx / 12;
        int c = idx - kk * 12;
        int col = (c >> 2) * HDIM + j0 + (c & 3);
        wh_s[idx] = Wh[(size_t)kk * HDIM3 + col];
    }

    float bn[JCHUNK];
#pragma unroll
    for (int c = 0; c < JCHUNK; c++) bn[c] = bhn[j0 + c];

    // Init: quarter 0 seeds g_hd[0] with duplicated h0, keeps own chunk in regs.
    float hn[JCHUNK];
    {
        float4 v = *(const float4*)&h0[(size_t)b * HDIM + j0];
        hn[0] = v.x; hn[1] = v.y; hn[2] = v.z; hn[3] = v.w;
        if (quarter == 0) {
#pragma unroll
            for (int c = 0; c < JCHUNK; c++)
                g_hd[0][(j0 + c) * BATCH + b] = pk2_(hn[c], hn[c]);
        }
    }
    gbar(1);

    for (int t = 0; t < T_STEPS; t++) {
        const u64* __restrict__ hp = g_hd[t & 1];
        u64* __restrict__ hq = g_hd[(t & 1) ^ 1];

        // Early-issue gi loads (quarter 0 only — it alone does the gates).
        float4 gr, gz, gn;
        if (quarter == 0) {
            const float* gi = &g_gi[((size_t)t * BATCH + b) * HDIM3];
            gr = *(const float4*)&gi[j0];
            gz = *(const float4*)&gi[HDIM + j0];
            gn = *(const float4*)&gi[2 * HDIM + j0];
        }

        u64 acc2[6];
#pragma unroll
        for (int c = 0; c < 6; c++) acc2[c] = 0ull;

        // Partial gh over k in [kbase, kbase+128), 8-deep pipelined h loads.
        u64 hv[8];
#pragma unroll
        for (int u = 0; u < 8; u++) hv[u] = hp[(kbase + u) * BATCH + b];

#pragma unroll 1
        for (int base = 0; base < KSPLIT; base += 8) {
            u64 hv_n[8];
            if (base + 8 < KSPLIT) {
#pragma unroll
                for (int u = 0; u < 8; u++)
                    hv_n[u] = hp[(kbase + base + 8 + u) * BATCH + b];
            }
#pragma unroll
            for (int u = 0; u < 8; u++) {
                const ulonglong2* w =
                    (const ulonglong2*)(wh_s + (kbase + base + u) * 12);
                ulonglong2 w01 = w[0], w23 = w[1], w45 = w[2];
                u64 h2 = hv[u];
                acc2[0] = ffma2_(h2, w01.x, acc2[0]);
                acc2[1] = ffma2_(h2, w01.y, acc2[1]);
                acc2[2] = ffma2_(h2, w23.x, acc2[2]);
                acc2[3] = ffma2_(h2, w23.y, acc2[3]);
                acc2[4] = ffma2_(h2, w45.x, acc2[4]);
                acc2[5] = ffma2_(h2, w45.y, acc2[5]);
            }
#pragma unroll
            for (int u = 0; u < 8; u++) hv[u] = hv_n[u];
        }

        // Cross-quarter reduction: quarters 1-3 dump, quarter 0 combines.
        if (quarter > 0) {
#pragma unroll
            for (int c = 0; c < 6; c++) red2[quarter - 1][c * BATCH + b] = acc2[c];
        }
        __syncthreads();

        if (quarter == 0) {
#pragma unroll
            for (int c = 0; c < 6; c++) {
                acc2[c] = fadd2_(acc2[c], red2[0][c * BATCH + b]);
                acc2[c] = fadd2_(acc2[c], fadd2_(red2[1][c * BATCH + b],
                                                 red2[2][c * BATCH + b]));
            }
            float a[12];
#pragma unroll
            for (int c = 0; c < 6; c++) upk2_(acc2[c], a[2 * c], a[2 * c + 1]);

            float giR[4] = {gr.x, gr.y, gr.z, gr.w};
            float giZ[4] = {gz.x, gz.y, gz.z, gz.w};
            float giN[4] = {gn.x, gn.y, gn.z, gn.w};

#pragma unroll
            for (int c = 0; c < JCHUNK; c++) {
                float r = fast_sigmoid(giR[c] + a[c]);
                float z = fast_sigmoid(giZ[c] + a[4 + c]);
                float n = fast_tanh(giN[c] + r * (a[8 + c] + bn[c]));
                float hnew = (1.0f - z) * n + z * hn[c];
                hn[c] = hnew;
                hq[(j0 + c) * BATCH + b] = pk2_(hnew, hnew);
            }

            *(float4*)&out_ys[((size_t)t * BATCH + b) * HDIM + j0] =
                make_float4(hn[0], hn[1], hn[2], hn[3]);
        }

        gbar((unsigned)t + 2);
    }

    if (out_h && quarter == 0) {
        *(float4*)&out_h[(size_t)b * HDIM + j0] =
            make_float4(hn[0], hn[1], hn[2], hn[3]);
    }
}

// ---------------------------------------------------------------------------
// kernel_launch: inputs per metadata order: x, h0, Wi, bi, Wh, bhn
// ---------------------------------------------------------------------------
extern "C" void kernel_launch(void* const* d_in, const int* in_sizes, int n_in,
                              void* d_out, int out_size)
{
    const float* x   = (const float*)d_in[0];   // [T, B, H]
    const float* h0  = (const float*)d_in[1];   // [B, H]
    const float* Wi  = (const float*)d_in[2];   // [H, 3H]
    const float* bi  = (const float*)d_in[3];   // [3H]
    const float* Wh  = (const float*)d_in[4];   // [H, 3H]
    const float* bhn = (const float*)d_in[5];   // [H]

    float* out = (float*)d_out;
    float* out_h;
    float* out_ys;
    const long long ys_elems = (long long)T_STEPS * BATCH * HDIM;
    if ((long long)out_size >= ys_elems + (long long)BATCH * HDIM) {
        out_h = out;                    // (h_final, ys) flattened in order
        out_ys = out + (size_t)BATCH * HDIM;
    } else {
        out_h = nullptr;                // ys only
        out_ys = out;
    }

    float* gi;
    cudaGetSymbolAddress((void**)&gi, g_gi);

    // 0) reset barrier epochs (graph-replay safe)
    reset_barrier_kernel<<<1, 32>>>();

    // 1) gi = x @ Wi + bi
    dim3 ggrid(HDIM3 / BN, (T_STEPS * BATCH) / BM);
    gemm_gi_kernel<<<ggrid, 256>>>(x, Wi, bi, gi);

    // 2) persistent GRU scan
    scan_kernel<<<SCAN_BLOCKS, SCAN_THREADS>>>(h0, Wh, bhn, out_h, out_ys);
}